// round 16
// baseline (speedup 1.0000x reference)
#include <cuda_runtime.h>
#include <cstdint>

// Problem constants
#define B_  32
#define P_  2048
#define D_  768
#define T_  3
#define H_  192
#define O_  128
#define NSPLIT 32
#define TOKS_PER_SPLIT (P_ / NSPLIT)   // 64
#define KBQ  48                         // split-K for proj_q
#define NKBQ (D_ / KBQ)                 // 16
#define KBG  96                         // split-E for proj_gk
#define NKBG (D_ / KBG)                 // 8
#define SCALE 0.036084391824351615f     // 1/sqrt(768)

// ---------------- device scratch ----------------
__device__ float g_qpart[NKBQ * T_ * D_];
__device__ float g_gs[T_ * D_];
__device__ float g_L[T_ * B_];                  // attn normalizers (atomic)
__device__ float g_xacc[T_ * B_ * D_];          // attn weighted sums (atomic)
__device__ float g_y1p[4][T_ * 32 * D_];
__device__ float g_y2p[4][T_ * 32 * D_];
__device__ float g_hp[4][T_ * 32 * H_];

// ---------------- K1: partial q[t,e] over k-block; ky==0 plane zeroes g_gs ----------------
// grid (6, NKBQ, T), 128 threads.
__global__ void proj_q_part_kernel(const float* __restrict__ tt,
                                   const float* __restrict__ Wq) {
    int t = blockIdx.z, ky = blockIdx.y;
    int e = blockIdx.x * 128 + threadIdx.x;
    if (ky == 0) g_gs[t * D_ + e] = 0.f;      // reset accumulator each replay
    int k0 = ky * KBQ;
    __shared__ float tts[KBQ];
    if (threadIdx.x < KBQ) tts[threadIdx.x] = tt[t * D_ + k0 + threadIdx.x];
    __syncthreads();
    const float* wp = Wq + (size_t)t * D_ * D_ + (size_t)k0 * D_ + e;
    float acc = 0.f;
    #pragma unroll 12
    for (int d = 0; d < KBQ; d++) acc += tts[d] * wp[(size_t)d * D_];
    g_qpart[(ky * T_ + t) * D_ + e] = acc;
}

// ---------------- K2: fused q-reduce + gs partial (atomic) + zero attn accumulators ----------
// grid (6, NKBG, T), 128 threads. q.bk dropped (softmax-invariant).
__global__ void proj_gk_part_kernel(const float* __restrict__ Wk,
                                    const float* __restrict__ bq) {
    int t = blockIdx.z, ky = blockIdx.y;
    int d = blockIdx.x * 128 + threadIdx.x;

    // zero g_xacc / g_L for this replay (runs strictly before attn).
    int linear = ((blockIdx.z * NKBG + blockIdx.y) * 6 + blockIdx.x) * 128 + threadIdx.x;
    ((float4*)g_xacc)[linear] = make_float4(0.f, 0.f, 0.f, 0.f);
    if (linear < T_ * B_) g_L[linear] = 0.f;

    int e0 = ky * KBG;
    __shared__ float qs[KBG];
    if (threadIdx.x < KBG) {
        int e = e0 + threadIdx.x;
        float s = bq[t * D_ + e];
        #pragma unroll
        for (int kq = 0; kq < NKBQ; kq++) s += g_qpart[(kq * T_ + t) * D_ + e];
        qs[threadIdx.x] = s;
    }
    __syncthreads();
    const float4* wp = (const float4*)(Wk + (size_t)t * D_ * D_ + (size_t)d * D_ + e0);
    float acc = 0.f;
    #pragma unroll
    for (int e4 = 0; e4 < KBG / 4; e4++) {
        float4 w = wp[e4];
        acc += w.x * qs[e4 * 4 + 0] + w.y * qs[e4 * 4 + 1]
             + w.z * qs[e4 * 4 + 2] + w.w * qs[e4 * 4 + 3];
    }
    atomicAdd(&g_gs[t * D_ + d], acc * SCALE);
}

// ---------------- K3: warp-autonomous attention — x touched ONCE ----------------
// Scores bounded (|s| << 1) -> exp(s) safe without max-subtraction.
// Each warp owns 16 tokens and a FULL private accumulator (3 tasks x 768 d as
// 18 float4 per lane). Butterfly reduction leaves the score in ALL lanes, so the
// weighted accumulation reuses the x registers loaded for scoring — no phase 3,
// no second L1 pass, no w_s, no in-loop barriers. Private accs merge via REDG.
// grid (NSPLIT, B), 128 threads (4 warps x 16 tokens = 64 tokens/split).
__global__ __launch_bounds__(128)
void attn_split_kernel(const float* __restrict__ x,
                       const void* __restrict__ mask_raw) {
    int b = blockIdx.y, sp = blockIdx.x;
    int tid = threadIdx.x;
    int lane = tid & 31, wid = tid >> 5;

    __shared__ __align__(16) float gs_s[T_][D_];
    __shared__ int mask_u8_s;

    // mask dtype probe: int32 bool array => first 32 words all in {0,1}.
    if (tid == 0) mask_u8_s = 0;
    __syncthreads();
    if (tid < 32) {
        unsigned v = ((const unsigned*)mask_raw)[tid];
        if (v > 1u) atomicOr(&mask_u8_s, 1);
    }

    for (int i = tid; i < T_ * D_; i += 128) ((float*)gs_s)[i] = g_gs[i];
    __syncthreads();                       // the ONLY block barrier
    const bool mask_is_u8 = (mask_u8_s != 0);
    const unsigned char* mb8  = (const unsigned char*)mask_raw + (size_t)b * P_;
    const int*           mb32 = (const int*)mask_raw + (size_t)b * P_;

    const float* xb = x + (size_t)b * P_ * D_;
    const float4* gs0_4 = (const float4*)gs_s[0];
    const float4* gs1_4 = (const float4*)gs_s[1];
    const float4* gs2_4 = (const float4*)gs_s[2];

    // private accumulators: 3 tasks x 6 float4 (d = 4*(lane+32j))
    float4 acc[T_][6];
    #pragma unroll
    for (int t = 0; t < T_; t++)
        #pragma unroll
        for (int j = 0; j < 6; j++) acc[t][j] = make_float4(0.f, 0.f, 0.f, 0.f);
    float l0 = 0.f, l1 = 0.f, l2 = 0.f;

    const int pw0 = sp * TOKS_PER_SPLIT + wid * 16;   // warp's 16 tokens

    for (int it = 0; it < 8; it++) {
        int p = pw0 + it * 2;
        const float4* xr0 = (const float4*)(xb + (size_t)(p + 0) * D_);
        const float4* xr1 = (const float4*)(xb + (size_t)(p + 1) * D_);

        // front-batch: 12 independent LDG.128 (MLP=12)
        float4 a0[6], a1[6];
        #pragma unroll
        for (int j = 0; j < 6; j++) {
            int idx = lane + 32 * j;
            a0[j] = xr0[idx];
            a1[j] = xr1[idx];
        }

        // scores (gs read once, shared by both tokens)
        float s00 = 0.f, s01 = 0.f, s02 = 0.f;
        float s10 = 0.f, s11 = 0.f, s12 = 0.f;
        #pragma unroll
        for (int j = 0; j < 6; j++) {
            int idx = lane + 32 * j;
            float4 g0 = gs0_4[idx], g1 = gs1_4[idx], g2 = gs2_4[idx];
            s00 += a0[j].x*g0.x + a0[j].y*g0.y + a0[j].z*g0.z + a0[j].w*g0.w;
            s01 += a0[j].x*g1.x + a0[j].y*g1.y + a0[j].z*g1.z + a0[j].w*g1.w;
            s02 += a0[j].x*g2.x + a0[j].y*g2.y + a0[j].z*g2.z + a0[j].w*g2.w;
            s10 += a1[j].x*g0.x + a1[j].y*g0.y + a1[j].z*g0.z + a1[j].w*g0.w;
            s11 += a1[j].x*g1.x + a1[j].y*g1.y + a1[j].z*g1.z + a1[j].w*g1.w;
            s12 += a1[j].x*g2.x + a1[j].y*g2.y + a1[j].z*g2.z + a1[j].w*g2.w;
        }
        // butterfly: every lane ends with the full sum
        #pragma unroll
        for (int off = 16; off; off >>= 1) {
            s00 += __shfl_xor_sync(0xffffffffu, s00, off);
            s01 += __shfl_xor_sync(0xffffffffu, s01, off);
            s02 += __shfl_xor_sync(0xffffffffu, s02, off);
            s10 += __shfl_xor_sync(0xffffffffu, s10, off);
            s11 += __shfl_xor_sync(0xffffffffu, s11, off);
            s12 += __shfl_xor_sync(0xffffffffu, s12, off);
        }

        // weights in-register (all lanes; mask loads are warp-broadcast L1 hits)
        bool mk0 = mask_is_u8 ? (mb8[p + 0] != 0) : (mb32[p + 0] != 0);
        bool mk1 = mask_is_u8 ? (mb8[p + 1] != 0) : (mb32[p + 1] != 0);
        float w00 = mk0 ? 0.f : __expf(s00);
        float w01 = mk0 ? 0.f : __expf(s01);
        float w02 = mk0 ? 0.f : __expf(s02);
        float w10 = mk1 ? 0.f : __expf(s10);
        float w11 = mk1 ? 0.f : __expf(s11);
        float w12 = mk1 ? 0.f : __expf(s12);
        l0 += w00 + w10; l1 += w01 + w11; l2 += w02 + w12;

        // accumulate from the SAME registers (no re-read of x)
        #pragma unroll
        for (int j = 0; j < 6; j++) {
            acc[0][j].x += w00*a0[j].x + w10*a1[j].x;
            acc[0][j].y += w00*a0[j].y + w10*a1[j].y;
            acc[0][j].z += w00*a0[j].z + w10*a1[j].z;
            acc[0][j].w += w00*a0[j].w + w10*a1[j].w;
            acc[1][j].x += w01*a0[j].x + w11*a1[j].x;
            acc[1][j].y += w01*a0[j].y + w11*a1[j].y;
            acc[1][j].z += w01*a0[j].z + w11*a1[j].z;
            acc[1][j].w += w01*a0[j].w + w11*a1[j].w;
            acc[2][j].x += w02*a0[j].x + w12*a1[j].x;
            acc[2][j].y += w02*a0[j].y + w12*a1[j].y;
            acc[2][j].z += w02*a0[j].z + w12*a1[j].z;
            acc[2][j].w += w02*a0[j].w + w12*a1[j].w;
        }
    }

    // merge: per-warp normalizers + private accumulators via global REDG
    if (lane == 0) {
        atomicAdd(&g_L[0 * B_ + b], l0);
        atomicAdd(&g_L[1 * B_ + b], l1);
        atomicAdd(&g_L[2 * B_ + b], l2);
    }
    #pragma unroll
    for (int t = 0; t < T_; t++) {
        float* base = &g_xacc[(size_t)(t * B_ + b) * D_];
        #pragma unroll
        for (int j = 0; j < 6; j++) {
            int d = 4 * (lane + 32 * j);
            atomicAdd(base + d + 0, acc[t][j].x);
            atomicAdd(base + d + 1, acc[t][j].y);
            atomicAdd(base + d + 2, acc[t][j].z);
            atomicAdd(base + d + 3, acc[t][j].w);
        }
    }
}

// ---------------- tiny GEMM: X fully staged, W double-stepped with reg prefetch ----------------
// k-range per call site is exactly 192 (4-way split for v/o/h1; h2 full K=192).
// XMODE: 0 = X0; 1 = X0+X1+X2+X3+xbias; 2 = that + xresid; 3 = gelu(sum+xbias);
//        4 = X0 row-scaled by 1/xbias[row] (attn normalize).
// OFINAL: 0 = raw partial; 1 = add obias.
#define KR 192
__device__ __forceinline__ float gelu_exact(float v) {
    return 0.5f * v * (1.0f + erff(v * 0.70710678118654752f));
}

template<int XMODE, int OFINAL>
__device__ __forceinline__
void gemm32_body(const float* __restrict__ X0, const float* __restrict__ X1,
                 const float* __restrict__ X2, const float* __restrict__ X3,
                 const float* __restrict__ xbias, const float* __restrict__ xresid,
                 const float* __restrict__ W, const float* __restrict__ obias,
                 float* __restrict__ Y, int K, int N, int k_begin) {
    int t = blockIdx.y;
    int tid = threadIdx.x;
    int tx = tid & 31;
    int ty = tid >> 5;              // 0..7
    int nc0 = blockIdx.x * 32;

    __shared__ __align__(16) float Xs[32][KR];    // 24 KB — staged ONCE
    __shared__ __align__(16) float Ws[96][32];    // 12 KB — two k-steps

    auto load_x = [&](int j) -> float4 {
        int r = j / (KR / 4), c4 = j % (KR / 4);
        size_t off = (size_t)(t * 32 + r) * K + k_begin + c4 * 4;
        float4 v = *(const float4*)(X0 + off);
        if (XMODE == 4) {
            float rl = 1.0f / xbias[t * 32 + r];
            v.x *= rl; v.y *= rl; v.z *= rl; v.w *= rl;
        }
        if (XMODE == 1 || XMODE == 2 || XMODE == 3) {
            float4 a = *(const float4*)(X1 + off);
            float4 b4 = *(const float4*)(X2 + off);
            float4 c4v = *(const float4*)(X3 + off);
            float4 bb = *(const float4*)(xbias + (size_t)t * K + k_begin + c4 * 4);
            v.x += a.x + b4.x + c4v.x + bb.x;
            v.y += a.y + b4.y + c4v.y + bb.y;
            v.z += a.z + b4.z + c4v.z + bb.z;
            v.w += a.w + b4.w + c4v.w + bb.w;
        }
        if (XMODE == 2) {
            float4 rr = *(const float4*)(xresid + (size_t)t * K + k_begin + c4 * 4);
            v.x += rr.x; v.y += rr.y; v.z += rr.z; v.w += rr.w;
        }
        if (XMODE == 3) {
            v.x = gelu_exact(v.x); v.y = gelu_exact(v.y);
            v.z = gelu_exact(v.z); v.w = gelu_exact(v.w);
        }
        return v;
    };
    auto load_w = [&](int j, int k0) -> float4 {
        int kk = j >> 3, c4 = j & 7;
        return *(const float4*)(W + ((size_t)t * K + k0 + kk) * N + nc0 + c4 * 4);
    };

    #pragma unroll
    for (int jj = 0; jj < 6; jj++)
        ((float4*)Xs)[tid + jj * 256] = load_x(tid + jj * 256);
    #pragma unroll
    for (int jj = 0; jj < 3; jj++)
        ((float4*)Ws)[tid + jj * 256] = load_w(tid + jj * 256, k_begin);
    __syncthreads();

    float4 pw[3];
    #pragma unroll
    for (int jj = 0; jj < 3; jj++)
        pw[jj] = load_w(tid + jj * 256, k_begin + 96);

    float acc[4] = {0.f, 0.f, 0.f, 0.f};
    #pragma unroll 8
    for (int k = 0; k < 96; k++) {
        float wv = Ws[k][tx];
        #pragma unroll
        for (int r = 0; r < 4; r++) acc[r] += Xs[ty + r * 8][k] * wv;
    }
    __syncthreads();
    #pragma unroll
    for (int jj = 0; jj < 3; jj++)
        ((float4*)Ws)[tid + jj * 256] = pw[jj];
    __syncthreads();
    #pragma unroll 8
    for (int k = 0; k < 96; k++) {
        float wv = Ws[k][tx];
        #pragma unroll
        for (int r = 0; r < 4; r++) acc[r] += Xs[ty + r * 8][96 + k] * wv;
    }

    int col = nc0 + tx;
    float bv = (OFINAL == 1) ? obias[t * N + col] : 0.f;
    #pragma unroll
    for (int r = 0; r < 4; r++) {
        int row = ty + r * 8;
        Y[(size_t)(t * 32 + row) * N + col] = acc[r] + bv;
    }
}

__global__ __launch_bounds__(256)
void gemm_v_kernel(const float* __restrict__ Wv) {
    int z = blockIdx.z;
    gemm32_body<4, 0>(g_xacc, nullptr, nullptr, nullptr, g_L, nullptr, Wv, nullptr,
                      g_y1p[z], D_, D_, z * 192);
}
__global__ __launch_bounds__(256)
void gemm_o_kernel(const float* __restrict__ Wo, const float* __restrict__ bv) {
    int z = blockIdx.z;
    gemm32_body<1, 0>(g_y1p[0], g_y1p[1], g_y1p[2], g_y1p[3], bv, nullptr, Wo, nullptr,
                      g_y2p[z], D_, D_, z * 192);
}
__global__ __launch_bounds__(256)
void gemm_h1_kernel(const float* __restrict__ h1w, const float* __restrict__ bo,
                    const float* __restrict__ tt) {
    int z = blockIdx.z;
    gemm32_body<2, 0>(g_y2p[0], g_y2p[1], g_y2p[2], g_y2p[3], bo, tt, h1w, nullptr,
                      g_hp[z], D_, H_, z * 192);
}
__global__ __launch_bounds__(256)
void gemm_h2_kernel(const float* __restrict__ h2w, const float* __restrict__ h1b,
                    const float* __restrict__ h2b, float* __restrict__ out) {
    gemm32_body<3, 1>(g_hp[0], g_hp[1], g_hp[2], g_hp[3], h1b, nullptr, h2w, h2b,
                      out, H_, O_, 0);
}

// ---------------- launch (kernel launches ONLY — graph-capture safe) ----------------
extern "C" void kernel_launch(void* const* d_in, const int* in_sizes, int n_in,
                              void* d_out, int out_size) {
    const float* x    = (const float*)d_in[0];
    const void*  mask = d_in[1];
    const float* tt   = (const float*)d_in[2];
    const float* Wq   = (const float*)d_in[3];
    const float* bq   = (const float*)d_in[4];
    const float* Wk   = (const float*)d_in[5];
    // d_in[6] = bk: dropped (softmax-invariant)
    const float* Wv   = (const float*)d_in[7];
    const float* bv   = (const float*)d_in[8];
    const float* Wo   = (const float*)d_in[9];
    const float* bo   = (const float*)d_in[10];
    const float* h1w  = (const float*)d_in[11];
    const float* h1b  = (const float*)d_in[12];
    const float* h2w  = (const float*)d_in[13];
    const float* h2b  = (const float*)d_in[14];
    float*       out  = (float*)d_out;

    proj_q_part_kernel<<<dim3(6, NKBQ, T_), 128>>>(tt, Wq);
    proj_gk_part_kernel<<<dim3(6, NKBG, T_), 128>>>(Wk, bq);
    attn_split_kernel<<<dim3(NSPLIT, B_), 128>>>(x, mask);
    gemm_v_kernel<<<dim3(24, T_, 4), 256>>>(Wv);
    gemm_o_kernel<<<dim3(24, T_, 4), 256>>>(Wo, bv);
    gemm_h1_kernel<<<dim3(6, T_, 4), 256>>>(h1w, bo, tt);
    gemm_h2_kernel<<<dim3(4, T_), 256>>>(h2w, h1b, h2b, out);
}

// round 17
// speedup vs baseline: 1.3815x; 1.3815x over previous
#include <cuda_runtime.h>
#include <cstdint>

// Problem constants
#define B_  32
#define P_  2048
#define D_  768
#define T_  3
#define H_  192
#define O_  128
#define NSPLIT 32
#define TOKS_PER_SPLIT (P_ / NSPLIT)   // 64
#define KBQ  48                         // split-K for proj_q
#define NKBQ (D_ / KBQ)                 // 16
#define KBG  96                         // split-E for proj_gk
#define NKBG (D_ / KBG)                 // 8
#define SCALE 0.036084391824351615f     // 1/sqrt(768)

// ---------------- device scratch ----------------
__device__ float g_qpart[NKBQ * T_ * D_];
__device__ float g_gs[T_ * D_];
__device__ float g_L[T_ * B_];                  // attn normalizers (atomic)
__device__ float g_xacc[T_ * B_ * D_];          // attn weighted sums (atomic)
__device__ float g_y1p[4][T_ * 32 * D_];
__device__ float g_y2p[4][T_ * 32 * D_];
__device__ float g_hp[4][T_ * 32 * H_];

// ---------------- K1: partial q[t,e] over k-block; ky==0 plane zeroes g_gs ----------------
// grid (6, NKBQ, T), 128 threads.
__global__ void proj_q_part_kernel(const float* __restrict__ tt,
                                   const float* __restrict__ Wq) {
    int t = blockIdx.z, ky = blockIdx.y;
    int e = blockIdx.x * 128 + threadIdx.x;
    if (ky == 0) g_gs[t * D_ + e] = 0.f;      // reset accumulator each replay
    int k0 = ky * KBQ;
    __shared__ float tts[KBQ];
    if (threadIdx.x < KBQ) tts[threadIdx.x] = tt[t * D_ + k0 + threadIdx.x];
    __syncthreads();
    const float* wp = Wq + (size_t)t * D_ * D_ + (size_t)k0 * D_ + e;
    float acc = 0.f;
    #pragma unroll 12
    for (int d = 0; d < KBQ; d++) acc += tts[d] * wp[(size_t)d * D_];
    g_qpart[(ky * T_ + t) * D_ + e] = acc;
}

// ---------------- K2: fused q-reduce + gs partial (atomic) + zero attn accumulators ----------
// grid (6, NKBG, T), 128 threads. q.bk dropped (softmax-invariant).
__global__ void proj_gk_part_kernel(const float* __restrict__ Wk,
                                    const float* __restrict__ bq) {
    int t = blockIdx.z, ky = blockIdx.y;
    int d = blockIdx.x * 128 + threadIdx.x;

    // zero g_xacc / g_L for this replay (runs strictly before attn).
    int linear = ((blockIdx.z * NKBG + blockIdx.y) * 6 + blockIdx.x) * 128 + threadIdx.x;
    ((float4*)g_xacc)[linear] = make_float4(0.f, 0.f, 0.f, 0.f);
    if (linear < T_ * B_) g_L[linear] = 0.f;

    int e0 = ky * KBG;
    __shared__ float qs[KBG];
    if (threadIdx.x < KBG) {
        int e = e0 + threadIdx.x;
        float s = bq[t * D_ + e];
        #pragma unroll
        for (int kq = 0; kq < NKBQ; kq++) s += g_qpart[(kq * T_ + t) * D_ + e];
        qs[threadIdx.x] = s;
    }
    __syncthreads();
    const float4* wp = (const float4*)(Wk + (size_t)t * D_ * D_ + (size_t)d * D_ + e0);
    float acc = 0.f;
    #pragma unroll
    for (int e4 = 0; e4 < KBG / 4; e4++) {
        float4 w = wp[e4];
        acc += w.x * qs[e4 * 4 + 0] + w.y * qs[e4 * 4 + 1]
             + w.z * qs[e4 * 4 + 2] + w.w * qs[e4 * 4 + 3];
    }
    atomicAdd(&g_gs[t * D_ + d], acc * SCALE);
}

// ---------------- K3: single-warp-block attention — x touched ONCE, R13's atomic count ----
// Scores bounded (|s| << 1) -> exp(s) safe without max-subtraction.
// ONE warp per block owns all 64 tokens of its split and a full private accumulator
// (3 tasks x 768 d = 18 float4/lane). Butterfly leaves scores in all lanes, so the
// accumulation reuses the x registers from scoring: x is read exactly once, no w_s,
// no block barriers. Latency is hidden by ~12 co-resident blocks/SM (one wave for
// the whole grid). Merge = 72 atomics/lane -> 2.36M total, SAME as the R13 best.
// grid (NSPLIT, B), 32 threads.
__global__ __launch_bounds__(32)
void attn_split_kernel(const float* __restrict__ x,
                       const void* __restrict__ mask_raw) {
    int b = blockIdx.y, sp = blockIdx.x;
    int lane = threadIdx.x;

    __shared__ __align__(16) float gs_s[T_][D_];
    __shared__ int mask_u8_s;

    // mask dtype probe: int32 bool array => first 32 words all in {0,1}.
    if (lane == 0) mask_u8_s = 0;
    __syncwarp();
    {
        unsigned v = ((const unsigned*)mask_raw)[lane];
        if (v > 1u) atomicOr(&mask_u8_s, 1);
    }

    // stage gs (2304 floats = 18 float4/lane, independent loads; L2 hits)
    {
        const float4* gsg = (const float4*)g_gs;
        #pragma unroll
        for (int j = 0; j < 18; j++)
            ((float4*)gs_s)[lane + 32 * j] = gsg[lane + 32 * j];
    }
    __syncwarp();
    const bool mask_is_u8 = (mask_u8_s != 0);
    const unsigned char* mb8  = (const unsigned char*)mask_raw + (size_t)b * P_;
    const int*           mb32 = (const int*)mask_raw + (size_t)b * P_;

    const float* xb = x + (size_t)b * P_ * D_;
    const float4* gs0_4 = (const float4*)gs_s[0];
    const float4* gs1_4 = (const float4*)gs_s[1];
    const float4* gs2_4 = (const float4*)gs_s[2];

    // private accumulators: 3 tasks x 6 float4 (d = 4*(lane+32j))
    float4 acc[T_][6];
    #pragma unroll
    for (int t = 0; t < T_; t++)
        #pragma unroll
        for (int j = 0; j < 6; j++) acc[t][j] = make_float4(0.f, 0.f, 0.f, 0.f);
    float l0 = 0.f, l1 = 0.f, l2 = 0.f;

    const int pw0 = sp * TOKS_PER_SPLIT;   // this warp's 64 tokens

    for (int it = 0; it < TOKS_PER_SPLIT / 2; it++) {   // 32 iterations of 2 tokens
        int p = pw0 + it * 2;
        const float4* xr0 = (const float4*)(xb + (size_t)(p + 0) * D_);
        const float4* xr1 = (const float4*)(xb + (size_t)(p + 1) * D_);

        // front-batch: 12 independent LDG.128 (MLP=12)
        float4 a0[6], a1[6];
        #pragma unroll
        for (int j = 0; j < 6; j++) {
            int idx = lane + 32 * j;
            a0[j] = xr0[idx];
            a1[j] = xr1[idx];
        }

        // scores (gs read once, shared by both tokens)
        float s00 = 0.f, s01 = 0.f, s02 = 0.f;
        float s10 = 0.f, s11 = 0.f, s12 = 0.f;
        #pragma unroll
        for (int j = 0; j < 6; j++) {
            int idx = lane + 32 * j;
            float4 g0 = gs0_4[idx], g1 = gs1_4[idx], g2 = gs2_4[idx];
            s00 += a0[j].x*g0.x + a0[j].y*g0.y + a0[j].z*g0.z + a0[j].w*g0.w;
            s01 += a0[j].x*g1.x + a0[j].y*g1.y + a0[j].z*g1.z + a0[j].w*g1.w;
            s02 += a0[j].x*g2.x + a0[j].y*g2.y + a0[j].z*g2.z + a0[j].w*g2.w;
            s10 += a1[j].x*g0.x + a1[j].y*g0.y + a1[j].z*g0.z + a1[j].w*g0.w;
            s11 += a1[j].x*g1.x + a1[j].y*g1.y + a1[j].z*g1.z + a1[j].w*g1.w;
            s12 += a1[j].x*g2.x + a1[j].y*g2.y + a1[j].z*g2.z + a1[j].w*g2.w;
        }
        // butterfly: every lane ends with the full sum
        #pragma unroll
        for (int off = 16; off; off >>= 1) {
            s00 += __shfl_xor_sync(0xffffffffu, s00, off);
            s01 += __shfl_xor_sync(0xffffffffu, s01, off);
            s02 += __shfl_xor_sync(0xffffffffu, s02, off);
            s10 += __shfl_xor_sync(0xffffffffu, s10, off);
            s11 += __shfl_xor_sync(0xffffffffu, s11, off);
            s12 += __shfl_xor_sync(0xffffffffu, s12, off);
        }

        // weights in-register (mask loads are warp-broadcast L1 hits)
        bool mk0 = mask_is_u8 ? (mb8[p + 0] != 0) : (mb32[p + 0] != 0);
        bool mk1 = mask_is_u8 ? (mb8[p + 1] != 0) : (mb32[p + 1] != 0);
        float w00 = mk0 ? 0.f : __expf(s00);
        float w01 = mk0 ? 0.f : __expf(s01);
        float w02 = mk0 ? 0.f : __expf(s02);
        float w10 = mk1 ? 0.f : __expf(s10);
        float w11 = mk1 ? 0.f : __expf(s11);
        float w12 = mk1 ? 0.f : __expf(s12);
        l0 += w00 + w10; l1 += w01 + w11; l2 += w02 + w12;

        // accumulate from the SAME registers (no re-read of x)
        #pragma unroll
        for (int j = 0; j < 6; j++) {
            acc[0][j].x += w00*a0[j].x + w10*a1[j].x;
            acc[0][j].y += w00*a0[j].y + w10*a1[j].y;
            acc[0][j].z += w00*a0[j].z + w10*a1[j].z;
            acc[0][j].w += w00*a0[j].w + w10*a1[j].w;
            acc[1][j].x += w01*a0[j].x + w11*a1[j].x;
            acc[1][j].y += w01*a0[j].y + w11*a1[j].y;
            acc[1][j].z += w01*a0[j].z + w11*a1[j].z;
            acc[1][j].w += w01*a0[j].w + w11*a1[j].w;
            acc[2][j].x += w02*a0[j].x + w12*a1[j].x;
            acc[2][j].y += w02*a0[j].y + w12*a1[j].y;
            acc[2][j].z += w02*a0[j].z + w12*a1[j].z;
            acc[2][j].w += w02*a0[j].w + w12*a1[j].w;
        }
    }

    // merge: per-warp normalizers + private accumulators via global REDG (2.36M total)
    if (lane == 0) {
        atomicAdd(&g_L[0 * B_ + b], l0);
        atomicAdd(&g_L[1 * B_ + b], l1);
        atomicAdd(&g_L[2 * B_ + b], l2);
    }
    #pragma unroll
    for (int t = 0; t < T_; t++) {
        float* base = &g_xacc[(size_t)(t * B_ + b) * D_];
        #pragma unroll
        for (int j = 0; j < 6; j++) {
            int d = 4 * (lane + 32 * j);
            atomicAdd(base + d + 0, acc[t][j].x);
            atomicAdd(base + d + 1, acc[t][j].y);
            atomicAdd(base + d + 2, acc[t][j].z);
            atomicAdd(base + d + 3, acc[t][j].w);
        }
    }
}

// ---------------- tiny GEMM: X fully staged, W double-stepped with reg prefetch ----------------
// k-range per call site is exactly 192 (4-way split for v/o/h1; h2 full K=192).
// XMODE: 0 = X0; 1 = X0+X1+X2+X3+xbias; 2 = that + xresid; 3 = gelu(sum+xbias);
//        4 = X0 row-scaled by 1/xbias[row] (attn normalize).
// OFINAL: 0 = raw partial; 1 = add obias.
#define KR 192
__device__ __forceinline__ float gelu_exact(float v) {
    return 0.5f * v * (1.0f + erff(v * 0.70710678118654752f));
}

template<int XMODE, int OFINAL>
__device__ __forceinline__
void gemm32_body(const float* __restrict__ X0, const float* __restrict__ X1,
                 const float* __restrict__ X2, const float* __restrict__ X3,
                 const float* __restrict__ xbias, const float* __restrict__ xresid,
                 const float* __restrict__ W, const float* __restrict__ obias,
                 float* __restrict__ Y, int K, int N, int k_begin) {
    int t = blockIdx.y;
    int tid = threadIdx.x;
    int tx = tid & 31;
    int ty = tid >> 5;              // 0..7
    int nc0 = blockIdx.x * 32;

    __shared__ __align__(16) float Xs[32][KR];    // 24 KB — staged ONCE
    __shared__ __align__(16) float Ws[96][32];    // 12 KB — two k-steps

    auto load_x = [&](int j) -> float4 {
        int r = j / (KR / 4), c4 = j % (KR / 4);
        size_t off = (size_t)(t * 32 + r) * K + k_begin + c4 * 4;
        float4 v = *(const float4*)(X0 + off);
        if (XMODE == 4) {
            float rl = 1.0f / xbias[t * 32 + r];
            v.x *= rl; v.y *= rl; v.z *= rl; v.w *= rl;
        }
        if (XMODE == 1 || XMODE == 2 || XMODE == 3) {
            float4 a = *(const float4*)(X1 + off);
            float4 b4 = *(const float4*)(X2 + off);
            float4 c4v = *(const float4*)(X3 + off);
            float4 bb = *(const float4*)(xbias + (size_t)t * K + k_begin + c4 * 4);
            v.x += a.x + b4.x + c4v.x + bb.x;
            v.y += a.y + b4.y + c4v.y + bb.y;
            v.z += a.z + b4.z + c4v.z + bb.z;
            v.w += a.w + b4.w + c4v.w + bb.w;
        }
        if (XMODE == 2) {
            float4 rr = *(const float4*)(xresid + (size_t)t * K + k_begin + c4 * 4);
            v.x += rr.x; v.y += rr.y; v.z += rr.z; v.w += rr.w;
        }
        if (XMODE == 3) {
            v.x = gelu_exact(v.x); v.y = gelu_exact(v.y);
            v.z = gelu_exact(v.z); v.w = gelu_exact(v.w);
        }
        return v;
    };
    auto load_w = [&](int j, int k0) -> float4 {
        int kk = j >> 3, c4 = j & 7;
        return *(const float4*)(W + ((size_t)t * K + k0 + kk) * N + nc0 + c4 * 4);
    };

    #pragma unroll
    for (int jj = 0; jj < 6; jj++)
        ((float4*)Xs)[tid + jj * 256] = load_x(tid + jj * 256);
    #pragma unroll
    for (int jj = 0; jj < 3; jj++)
        ((float4*)Ws)[tid + jj * 256] = load_w(tid + jj * 256, k_begin);
    __syncthreads();

    float4 pw[3];
    #pragma unroll
    for (int jj = 0; jj < 3; jj++)
        pw[jj] = load_w(tid + jj * 256, k_begin + 96);

    float acc[4] = {0.f, 0.f, 0.f, 0.f};
    #pragma unroll 8
    for (int k = 0; k < 96; k++) {
        float wv = Ws[k][tx];
        #pragma unroll
        for (int r = 0; r < 4; r++) acc[r] += Xs[ty + r * 8][k] * wv;
    }
    __syncthreads();
    #pragma unroll
    for (int jj = 0; jj < 3; jj++)
        ((float4*)Ws)[tid + jj * 256] = pw[jj];
    __syncthreads();
    #pragma unroll 8
    for (int k = 0; k < 96; k++) {
        float wv = Ws[k][tx];
        #pragma unroll
        for (int r = 0; r < 4; r++) acc[r] += Xs[ty + r * 8][96 + k] * wv;
    }

    int col = nc0 + tx;
    float bv = (OFINAL == 1) ? obias[t * N + col] : 0.f;
    #pragma unroll
    for (int r = 0; r < 4; r++) {
        int row = ty + r * 8;
        Y[(size_t)(t * 32 + row) * N + col] = acc[r] + bv;
    }
}

__global__ __launch_bounds__(256)
void gemm_v_kernel(const float* __restrict__ Wv) {
    int z = blockIdx.z;
    gemm32_body<4, 0>(g_xacc, nullptr, nullptr, nullptr, g_L, nullptr, Wv, nullptr,
                      g_y1p[z], D_, D_, z * 192);
}
__global__ __launch_bounds__(256)
void gemm_o_kernel(const float* __restrict__ Wo, const float* __restrict__ bv) {
    int z = blockIdx.z;
    gemm32_body<1, 0>(g_y1p[0], g_y1p[1], g_y1p[2], g_y1p[3], bv, nullptr, Wo, nullptr,
                      g_y2p[z], D_, D_, z * 192);
}
__global__ __launch_bounds__(256)
void gemm_h1_kernel(const float* __restrict__ h1w, const float* __restrict__ bo,
                    const float* __restrict__ tt) {
    int z = blockIdx.z;
    gemm32_body<2, 0>(g_y2p[0], g_y2p[1], g_y2p[2], g_y2p[3], bo, tt, h1w, nullptr,
                      g_hp[z], D_, H_, z * 192);
}
__global__ __launch_bounds__(256)
void gemm_h2_kernel(const float* __restrict__ h2w, const float* __restrict__ h1b,
                    const float* __restrict__ h2b, float* __restrict__ out) {
    gemm32_body<3, 1>(g_hp[0], g_hp[1], g_hp[2], g_hp[3], h1b, nullptr, h2w, h2b,
                      out, H_, O_, 0);
}

// ---------------- launch (kernel launches ONLY — graph-capture safe) ----------------
extern "C" void kernel_launch(void* const* d_in, const int* in_sizes, int n_in,
                              void* d_out, int out_size) {
    const float* x    = (const float*)d_in[0];
    const void*  mask = d_in[1];
    const float* tt   = (const float*)d_in[2];
    const float* Wq   = (const float*)d_in[3];
    const float* bq   = (const float*)d_in[4];
    const float* Wk   = (const float*)d_in[5];
    // d_in[6] = bk: dropped (softmax-invariant)
    const float* Wv   = (const float*)d_in[7];
    const float* bv   = (const float*)d_in[8];
    const float* Wo   = (const float*)d_in[9];
    const float* bo   = (const float*)d_in[10];
    const float* h1w  = (const float*)d_in[11];
    const float* h1b  = (const float*)d_in[12];
    const float* h2w  = (const float*)d_in[13];
    const float* h2b  = (const float*)d_in[14];
    float*       out  = (float*)d_out;

    proj_q_part_kernel<<<dim3(6, NKBQ, T_), 128>>>(tt, Wq);
    proj_gk_part_kernel<<<dim3(6, NKBG, T_), 128>>>(Wk, bq);
    attn_split_kernel<<<dim3(NSPLIT, B_), 32>>>(x, mask);
    gemm_v_kernel<<<dim3(24, T_, 4), 256>>>(Wv);
    gemm_o_kernel<<<dim3(24, T_, 4), 256>>>(Wo, bv);
    gemm_h1_kernel<<<dim3(6, T_, 4), 256>>>(h1w, bo, tt);
    gemm_h2_kernel<<<dim3(4, T_), 256>>>(h2w, h1b, h2b, out);
}